// round 1
// baseline (speedup 1.0000x reference)
#include <cuda_runtime.h>
#include <math.h>

// ---------------- problem constants ----------------
#define B_    2
#define S_    2048
#define DIM_  2048
#define H_    16
#define NOPE_ 128
#define ROPE_ 64
#define VDIM_ 128
#define QR_   1024
#define KVR_  512
#define MTOK  (B_*S_)          // 4096
#define QKD   (NOPE_+ROPE_)    // 192
#define BH_   (B_*H_)          // 32

// ---------------- scratch (static device memory; no allocations) -------------
__device__ float g_qc   [(long long)MTOK*QR_];          // 16 MB
__device__ float g_qnope[(long long)MTOK*H_*NOPE_];     // 32 MB
__device__ float g_qpe  [(long long)MTOK*H_*ROPE_];     // 16 MB
__device__ float g_kvc  [(long long)MTOK*KVR_];         //  8 MB
__device__ float g_kvup [(long long)MTOK*H_*(NOPE_+VDIM_)]; // 64 MB
__device__ float g_krope[(long long)MTOK*ROPE_];        //  1 MB
__device__ float g_Q    [(long long)BH_*S_*QKD];        // 50 MB
__device__ float g_K    [(long long)BH_*S_*QKD];        // 50 MB
__device__ float g_V    [(long long)BH_*S_*VDIM_];      // 33 MB
__device__ float g_sc   [(long long)BH_*S_*S_];         // 512 MB
__device__ float g_attn [(long long)MTOK*H_*VDIM_];     // 32 MB

// ---------------- generic 64x64x32 tiled SGEMM ----------------
// C[M,N] = A[M,K] * op(B).  BT=true: B stored [N,K] (NT gemm).  BT=false: B stored [K,N] (NN).
// CAUSAL: 0 none, 1 skip blocks fully above diagonal (requires M==N tiles), 2 limit K to (bm+1)*64.
// ATTNC: write C into [b, s, h*VDIM + n] layout (batch = b*H + h).
template<bool BT, int CAUSAL, bool ATTNC>
__global__ void gemm64(const float* __restrict__ A, const float* __restrict__ Bm,
                       float* __restrict__ C, int M, int N, int K,
                       long long sA, long long sB, long long sC)
{
    const int bm = blockIdx.y, bn = blockIdx.x, bz = blockIdx.z;
    if (CAUSAL == 1 && bn > bm) return;

    const float* Ab = A + (long long)bz * sA;
    const float* Bb = Bm + (long long)bz * sB;
    float* Cb;
    int ldc;
    if (ATTNC) {
        int b = bz / H_, h = bz % H_;
        Cb = C + (long long)b * S_ * (H_ * VDIM_) + (long long)h * VDIM_;
        ldc = H_ * VDIM_;
    } else {
        Cb = C + (long long)bz * sC;
        ldc = N;
    }

    const int kEnd = (CAUSAL == 2) ? min(K, (bm + 1) * 64) : K;

    __shared__ float As[64 * 33];
    __shared__ float Bs[64 * 33];

    const int tid = threadIdx.x;
    const int tx = tid & 15, ty = tid >> 4;
    float acc[4][4] = {};

    for (int k0 = 0; k0 < kEnd; k0 += 32) {
        #pragma unroll
        for (int l = 0; l < 8; l++) {
            int idx = tid + l * 256;
            int r = idx >> 5, c = idx & 31;
            As[r * 33 + c] = Ab[(long long)(bm * 64 + r) * K + k0 + c];
        }
        if (BT) {
            #pragma unroll
            for (int l = 0; l < 8; l++) {
                int idx = tid + l * 256;
                int r = idx >> 5, c = idx & 31;
                Bs[r * 33 + c] = Bb[(long long)(bn * 64 + r) * K + k0 + c];
            }
        } else {
            #pragma unroll
            for (int l = 0; l < 8; l++) {
                int idx = tid + l * 256;
                int kk = idx >> 6, n = idx & 63;
                Bs[kk * 65 + n] = Bb[(long long)(k0 + kk) * N + bn * 64 + n];
            }
        }
        __syncthreads();
        #pragma unroll
        for (int kk = 0; kk < 32; kk++) {
            float a[4], b[4];
            #pragma unroll
            for (int i = 0; i < 4; i++) a[i] = As[(ty * 4 + i) * 33 + kk];
            #pragma unroll
            for (int j = 0; j < 4; j++)
                b[j] = BT ? Bs[(tx * 4 + j) * 33 + kk] : Bs[kk * 65 + tx * 4 + j];
            #pragma unroll
            for (int i = 0; i < 4; i++)
                #pragma unroll
                for (int j = 0; j < 4; j++)
                    acc[i][j] += a[i] * b[j];
        }
        __syncthreads();
    }
    #pragma unroll
    for (int i = 0; i < 4; i++)
        #pragma unroll
        for (int j = 0; j < 4; j++)
            Cb[(long long)(bm * 64 + ty * 4 + i) * ldc + bn * 64 + tx * 4 + j] = acc[i][j];
}

// ---------------- RMSNorm (in-place, one block per row) ----------------
__global__ void rmsnorm_k(float* __restrict__ x, const float* __restrict__ w, int N)
{
    float* p = x + (long long)blockIdx.x * N;
    int tid = threadIdx.x;
    float ss = 0.f;
    for (int i = tid; i < N; i += 256) { float v = p[i]; ss += v * v; }
    __shared__ float red[256];
    red[tid] = ss; __syncthreads();
    for (int s = 128; s > 0; s >>= 1) { if (tid < s) red[tid] += red[tid + s]; __syncthreads(); }
    float scale = rsqrtf(red[0] / N + 1e-6f);
    for (int i = tid; i < N; i += 256) p[i] = p[i] * scale * w[i];
}

// ---------------- RoPE on q_pe [MTOK, H*ROPE] ----------------
__global__ void rope_q_k(float* __restrict__ qpe)
{
    int row = blockIdx.x;              // b*S + s
    int s = row % S_;
    float* base = qpe + (long long)row * (H_ * ROPE_);
    for (int idx = threadIdx.x; idx < H_ * (ROPE_ / 2); idx += 256) {
        int h = idx >> 5, i = idx & 31;
        float fr = (float)s * powf(10000.f, -(2.f * i) / (float)ROPE_);
        float sn, c; sincosf(fr, &sn, &c);
        float* q = base + h * ROPE_;
        float x1 = q[2 * i], x2 = q[2 * i + 1];
        q[2 * i]     = x1 * c - x2 * sn;
        q[2 * i + 1] = x1 * sn + x2 * c;
    }
}

// ---------------- RoPE on k_rope [MTOK, ROPE] ----------------
__global__ void rope_kr_k(float* __restrict__ kr)
{
    int row = blockIdx.x;
    int s = row % S_;
    float* q = kr + (long long)row * ROPE_;
    int i = threadIdx.x;               // 32 threads = 32 pairs
    float fr = (float)s * powf(10000.f, -(2.f * i) / (float)ROPE_);
    float sn, c; sincosf(fr, &sn, &c);
    float x1 = q[2 * i], x2 = q[2 * i + 1];
    q[2 * i]     = x1 * c - x2 * sn;
    q[2 * i + 1] = x1 * sn + x2 * c;
}

// ---------------- pack Q/K/V into [b,h,s,d] contiguous; fold softmax scale into Q ---
__global__ void pack_k(const float* __restrict__ qn, const float* __restrict__ qp,
                       const float* __restrict__ kvu, const float* __restrict__ kr,
                       float* __restrict__ Q, float* __restrict__ K, float* __restrict__ V)
{
    int bsh = blockIdx.x;
    int h = bsh % H_;
    int bs = bsh / H_;
    int b = bs / S_, s = bs % S_;
    long long out = ((long long)(b * H_ + h) * S_ + s);
    const float scale = 0.07216878364870323f;   // 1/sqrt(192)
    for (int d = threadIdx.x; d < QKD; d += 256) {
        float qv = (d < NOPE_)
            ? qn[(long long)bs * (H_ * NOPE_) + h * NOPE_ + d]
            : qp[(long long)bs * (H_ * ROPE_) + h * ROPE_ + (d - NOPE_)];
        Q[out * QKD + d] = qv * scale;
        float kv = (d < NOPE_)
            ? kvu[(long long)bs * (H_ * (NOPE_ + VDIM_)) + h * (NOPE_ + VDIM_) + d]
            : kr[(long long)bs * ROPE_ + (d - NOPE_)];
        K[out * QKD + d] = kv;
    }
    for (int v = threadIdx.x; v < VDIM_; v += 256) {
        V[out * VDIM_ + v] =
            kvu[(long long)bs * (H_ * (NOPE_ + VDIM_)) + h * (NOPE_ + VDIM_) + NOPE_ + v];
    }
}

// ---------------- causal softmax (in-place on scores), zero-fill to 64-boundary ----
__global__ void softmax_causal(float* __restrict__ sc)
{
    int i = blockIdx.x;
    long long bh = blockIdx.y;
    float* row = sc + (bh * S_ + i) * (long long)S_;
    int len = i + 1;
    int tid = threadIdx.x;
    __shared__ float red[256];

    float mx = -1e30f;
    for (int j = tid; j < len; j += 256) mx = fmaxf(mx, row[j]);
    red[tid] = mx; __syncthreads();
    for (int s = 128; s > 0; s >>= 1) { if (tid < s) red[tid] = fmaxf(red[tid], red[tid + s]); __syncthreads(); }
    mx = red[0]; __syncthreads();

    float sum = 0.f;
    for (int j = tid; j < len; j += 256) { float e = expf(row[j] - mx); row[j] = e; sum += e; }
    red[tid] = sum; __syncthreads();
    for (int s = 128; s > 0; s >>= 1) { if (tid < s) red[tid] += red[tid + s]; __syncthreads(); }
    float inv = 1.f / red[0];

    for (int j = tid; j < len; j += 256) row[j] *= inv;
    int rounded = (len + 63) & ~63;
    for (int j = len + tid; j < rounded; j += 256) row[j] = 0.f;
}

// ---------------- launch ----------------
extern "C" void kernel_launch(void* const* d_in, const int* in_sizes, int n_in,
                              void* d_out, int out_size)
{
    const float* x        = (const float*)d_in[0];
    const float* wq_down  = (const float*)d_in[1];
    const float* q_norm   = (const float*)d_in[2];
    const float* wq_up    = (const float*)d_in[3];
    const float* wq_rope  = (const float*)d_in[4];
    const float* wkv_down = (const float*)d_in[5];
    const float* kv_norm  = (const float*)d_in[6];
    const float* wkv_up   = (const float*)d_in[7];
    const float* wk_rope  = (const float*)d_in[8];
    const float* wo       = (const float*)d_in[9];
    float* out = (float*)d_out;

    float *qc, *qn, *qp, *kvc, *kvu, *kr, *Q, *K, *V, *sc, *attn;
    cudaGetSymbolAddress((void**)&qc,   g_qc);
    cudaGetSymbolAddress((void**)&qn,   g_qnope);
    cudaGetSymbolAddress((void**)&qp,   g_qpe);
    cudaGetSymbolAddress((void**)&kvc,  g_kvc);
    cudaGetSymbolAddress((void**)&kvu,  g_kvup);
    cudaGetSymbolAddress((void**)&kr,   g_krope);
    cudaGetSymbolAddress((void**)&Q,    g_Q);
    cudaGetSymbolAddress((void**)&K,    g_K);
    cudaGetSymbolAddress((void**)&V,    g_V);
    cudaGetSymbolAddress((void**)&sc,   g_sc);
    cudaGetSymbolAddress((void**)&attn, g_attn);

    dim3 blk(256);

    // q_c = rmsnorm(x @ wq_down^T)
    gemm64<true,0,false><<<dim3(QR_/64, MTOK/64, 1), blk>>>(x, wq_down, qc, MTOK, QR_, DIM_, 0, 0, 0);
    rmsnorm_k<<<MTOK, 256>>>(qc, q_norm, QR_);
    // q_nope = q_c @ wq_up^T ; q_pe = q_c @ wq_rope^T
    gemm64<true,0,false><<<dim3((H_*NOPE_)/64, MTOK/64, 1), blk>>>(qc, wq_up,   qn, MTOK, H_*NOPE_, QR_, 0, 0, 0);
    gemm64<true,0,false><<<dim3((H_*ROPE_)/64, MTOK/64, 1), blk>>>(qc, wq_rope, qp, MTOK, H_*ROPE_, QR_, 0, 0, 0);
    // kv_c = rmsnorm(x @ wkv_down^T); kv_up = kv_c @ wkv_up^T
    gemm64<true,0,false><<<dim3(KVR_/64, MTOK/64, 1), blk>>>(x, wkv_down, kvc, MTOK, KVR_, DIM_, 0, 0, 0);
    rmsnorm_k<<<MTOK, 256>>>(kvc, kv_norm, KVR_);
    gemm64<true,0,false><<<dim3((H_*(NOPE_+VDIM_))/64, MTOK/64, 1), blk>>>(kvc, wkv_up, kvu, MTOK, H_*(NOPE_+VDIM_), KVR_, 0, 0, 0);
    // shared k_rope = x @ wk_rope^T
    gemm64<true,0,false><<<dim3(ROPE_/64, MTOK/64, 1), blk>>>(x, wk_rope, kr, MTOK, ROPE_, DIM_, 0, 0, 0);
    // RoPE
    rope_q_k <<<MTOK, 256>>>(qp);
    rope_kr_k<<<MTOK, 32>>>(kr);
    // pack Q/K/V [b,h,s,d]
    pack_k<<<MTOK * H_, 256>>>(qn, qp, kvu, kr, Q, K, V);
    // scores = Q @ K^T (batched over b*h, causal block skip)
    gemm64<true,1,false><<<dim3(S_/64, S_/64, BH_), blk>>>(
        Q, K, sc, S_, S_, QKD,
        (long long)S_*QKD, (long long)S_*QKD, (long long)S_*S_);
    // causal softmax
    softmax_causal<<<dim3(S_, BH_), 256>>>(sc);
    // attn = P @ V (batched, K limited causally, write into [b,s,h*v])
    gemm64<false,2,true><<<dim3(VDIM_/64, S_/64, BH_), blk>>>(
        sc, V, attn, S_, VDIM_, S_,
        (long long)S_*S_, (long long)S_*VDIM_, 0);
    // out = attn @ wo^T
    gemm64<true,0,false><<<dim3(DIM_/64, MTOK/64, 1), blk>>>(attn, wo, out, MTOK, DIM_, DIM_, 0, 0, 0);
}

// round 2
// speedup vs baseline: 1.6424x; 1.6424x over previous
#include <cuda_runtime.h>
#include <math.h>
#include <mma.h>
using namespace nvcuda;

// ---------------- problem constants ----------------
#define B_    2
#define S_    2048
#define DIM_  2048
#define H_    16
#define NOPE_ 128
#define ROPE_ 64
#define VDIM_ 128
#define QR_   1024
#define KVR_  512
#define MTOK  (B_*S_)          // 4096
#define QKD   (NOPE_+ROPE_)    // 192
#define BH_   (B_*H_)          // 32

// ---------------- scratch (static device memory; no allocations) -------------
__device__ float g_qc   [(long long)MTOK*QR_];
__device__ float g_qnope[(long long)MTOK*H_*NOPE_];
__device__ float g_qpe  [(long long)MTOK*H_*ROPE_];
__device__ float g_kvc  [(long long)MTOK*KVR_];
__device__ float g_kvup [(long long)MTOK*H_*(NOPE_+VDIM_)];
__device__ float g_krope[(long long)MTOK*ROPE_];
__device__ float g_Q    [(long long)BH_*S_*QKD];
__device__ float g_K    [(long long)BH_*S_*QKD];
__device__ float g_V    [(long long)BH_*S_*VDIM_];
__device__ float g_sc   [(long long)BH_*S_*S_];
__device__ float g_attn [(long long)MTOK*H_*VDIM_];

// =====================================================================
// TF32 tensor-core GEMM, 128x128 block tile, BK=32, 8 warps (64x32 each)
// C[M,N] = A[M,K] * op(B). BT=true: B stored [N,K] (NT). BT=false: [K,N] (NN).
// CAUSAL: 0 none, 1 skip block cols above diagonal (M==N), 2 limit K to (bm+1)*128.
// ATTNC: write C into [b, s, h*VDIM + n] layout (batch z = b*H + h).
// =====================================================================
template<bool BT, int CAUSAL, bool ATTNC>
__global__ __launch_bounds__(256, 2)
void gemm_tf32(const float* __restrict__ A, const float* __restrict__ Bm,
               float* __restrict__ C, int M, int N, int K,
               long long sA, long long sB, long long sC)
{
    const int bm = blockIdx.y, bn = blockIdx.x, bz = blockIdx.z;
    if (CAUSAL == 1 && bn > bm) return;

    const float* Ab = A + (long long)bz * sA;
    const float* Bb = Bm + (long long)bz * sB;
    float* Cb;
    int ldc;
    if (ATTNC) {
        int b = bz / H_, h = bz % H_;
        Cb = C + (long long)b * S_ * (H_ * VDIM_) + (long long)h * VDIM_;
        ldc = H_ * VDIM_;
    } else {
        Cb = C + (long long)bz * sC;
        ldc = N;
    }

    const int kEnd = (CAUSAL == 2) ? min(K, (bm + 1) * 128) : K;

    __shared__ float As[128 * 36];
    __shared__ float Bs[128 * 36];   // NN mode uses 32*132 <= 128*36

    const int tid = threadIdx.x;
    const int w = tid >> 5;
    const int wm = w >> 2;           // 0..1
    const int wn = w & 3;            // 0..3

    wmma::fragment<wmma::accumulator, 16, 16, 8, float> cf[4][2];
    #pragma unroll
    for (int i = 0; i < 4; i++)
        #pragma unroll
        for (int j = 0; j < 2; j++)
            wmma::fill_fragment(cf[i][j], 0.0f);

    for (int k0 = 0; k0 < kEnd; k0 += 32) {
        // ---- load A tile 128x32 (float4) ----
        #pragma unroll
        for (int l = 0; l < 4; l++) {
            int idx = tid + l * 256;
            int r = idx >> 3, c4 = (idx & 7) << 2;
            *(float4*)&As[r * 36 + c4] =
                *(const float4*)&Ab[(long long)(bm * 128 + r) * K + k0 + c4];
        }
        // ---- load B tile ----
        if constexpr (BT) {
            #pragma unroll
            for (int l = 0; l < 4; l++) {
                int idx = tid + l * 256;
                int r = idx >> 3, c4 = (idx & 7) << 2;
                *(float4*)&Bs[r * 36 + c4] =
                    *(const float4*)&Bb[(long long)(bn * 128 + r) * K + k0 + c4];
            }
        } else {
            #pragma unroll
            for (int l = 0; l < 4; l++) {
                int idx = tid + l * 256;
                int r = idx >> 5, c4 = (idx & 31) << 2;
                *(float4*)&Bs[r * 132 + c4] =
                    *(const float4*)&Bb[(long long)(k0 + r) * N + bn * 128 + c4];
            }
        }
        __syncthreads();

        #pragma unroll
        for (int kk = 0; kk < 4; kk++) {
            wmma::fragment<wmma::matrix_a, 16, 16, 8, wmma::precision::tf32, wmma::row_major> af[4];
            #pragma unroll
            for (int i = 0; i < 4; i++) {
                wmma::load_matrix_sync(af[i], &As[(wm * 64 + i * 16) * 36 + kk * 8], 36);
                #pragma unroll
                for (int t = 0; t < af[i].num_elements; t++)
                    af[i].x[t] = wmma::__float_to_tf32(af[i].x[t]);
            }
            if constexpr (BT) {
                wmma::fragment<wmma::matrix_b, 16, 16, 8, wmma::precision::tf32, wmma::col_major> bf[2];
                #pragma unroll
                for (int j = 0; j < 2; j++) {
                    wmma::load_matrix_sync(bf[j], &Bs[(wn * 32 + j * 16) * 36 + kk * 8], 36);
                    #pragma unroll
                    for (int t = 0; t < bf[j].num_elements; t++)
                        bf[j].x[t] = wmma::__float_to_tf32(bf[j].x[t]);
                }
                #pragma unroll
                for (int i = 0; i < 4; i++)
                    #pragma unroll
                    for (int j = 0; j < 2; j++)
                        wmma::mma_sync(cf[i][j], af[i], bf[j], cf[i][j]);
            } else {
                wmma::fragment<wmma::matrix_b, 16, 16, 8, wmma::precision::tf32, wmma::row_major> bf[2];
                #pragma unroll
                for (int j = 0; j < 2; j++) {
                    wmma::load_matrix_sync(bf[j], &Bs[(kk * 8) * 132 + wn * 32 + j * 16], 132);
                    #pragma unroll
                    for (int t = 0; t < bf[j].num_elements; t++)
                        bf[j].x[t] = wmma::__float_to_tf32(bf[j].x[t]);
                }
                #pragma unroll
                for (int i = 0; i < 4; i++)
                    #pragma unroll
                    for (int j = 0; j < 2; j++)
                        wmma::mma_sync(cf[i][j], af[i], bf[j], cf[i][j]);
            }
        }
        __syncthreads();
    }

    #pragma unroll
    for (int i = 0; i < 4; i++)
        #pragma unroll
        for (int j = 0; j < 2; j++)
            wmma::store_matrix_sync(
                &Cb[(long long)(bm * 128 + wm * 64 + i * 16) * ldc + bn * 128 + wn * 32 + j * 16],
                cf[i][j], (unsigned)ldc, wmma::mem_row_major);
}

// ---------------- fp32 fallback SGEMM (only for tiny k_rope, N=64) ----------------
__global__ void gemm64(const float* __restrict__ A, const float* __restrict__ Bm,
                       float* __restrict__ C, int M, int N, int K)
{
    const int bm = blockIdx.y, bn = blockIdx.x;
    __shared__ float As[64 * 33];
    __shared__ float Bs[64 * 33];
    const int tid = threadIdx.x;
    const int tx = tid & 15, ty = tid >> 4;
    float acc[4][4] = {};
    for (int k0 = 0; k0 < K; k0 += 32) {
        #pragma unroll
        for (int l = 0; l < 8; l++) {
            int idx = tid + l * 256;
            int r = idx >> 5, c = idx & 31;
            As[r * 33 + c] = A[(long long)(bm * 64 + r) * K + k0 + c];
            Bs[r * 33 + c] = Bm[(long long)(bn * 64 + r) * K + k0 + c];
        }
        __syncthreads();
        #pragma unroll
        for (int kk = 0; kk < 32; kk++) {
            float a[4], b[4];
            #pragma unroll
            for (int i = 0; i < 4; i++) a[i] = As[(ty * 4 + i) * 33 + kk];
            #pragma unroll
            for (int j = 0; j < 4; j++) b[j] = Bs[(tx * 4 + j) * 33 + kk];
            #pragma unroll
            for (int i = 0; i < 4; i++)
                #pragma unroll
                for (int j = 0; j < 4; j++)
                    acc[i][j] += a[i] * b[j];
        }
        __syncthreads();
    }
    #pragma unroll
    for (int i = 0; i < 4; i++)
        #pragma unroll
        for (int j = 0; j < 4; j++)
            C[(long long)(bm * 64 + ty * 4 + i) * N + bn * 64 + tx * 4 + j] = acc[i][j];
}

// ---------------- RMSNorm (in-place, one block per row) ----------------
__global__ void rmsnorm_k(float* __restrict__ x, const float* __restrict__ w, int N)
{
    float* p = x + (long long)blockIdx.x * N;
    int tid = threadIdx.x;
    float ss = 0.f;
    for (int i = tid; i < N; i += 256) { float v = p[i]; ss += v * v; }
    __shared__ float red[256];
    red[tid] = ss; __syncthreads();
    for (int s = 128; s > 0; s >>= 1) { if (tid < s) red[tid] += red[tid + s]; __syncthreads(); }
    float scale = rsqrtf(red[0] / N + 1e-6f);
    for (int i = tid; i < N; i += 256) p[i] = p[i] * scale * w[i];
}

// ---------------- RoPE on q_pe [MTOK, H*ROPE] ----------------
__global__ void rope_q_k(float* __restrict__ qpe)
{
    int row = blockIdx.x;
    int s = row % S_;
    float* base = qpe + (long long)row * (H_ * ROPE_);
    for (int idx = threadIdx.x; idx < H_ * (ROPE_ / 2); idx += 256) {
        int h = idx >> 5, i = idx & 31;
        float fr = (float)s * powf(10000.f, -(2.f * i) / (float)ROPE_);
        float sn, c; sincosf(fr, &sn, &c);
        float* q = base + h * ROPE_;
        float x1 = q[2 * i], x2 = q[2 * i + 1];
        q[2 * i]     = x1 * c - x2 * sn;
        q[2 * i + 1] = x1 * sn + x2 * c;
    }
}

// ---------------- RoPE on k_rope [MTOK, ROPE] ----------------
__global__ void rope_kr_k(float* __restrict__ kr)
{
    int row = blockIdx.x;
    int s = row % S_;
    float* q = kr + (long long)row * ROPE_;
    int i = threadIdx.x;
    float fr = (float)s * powf(10000.f, -(2.f * i) / (float)ROPE_);
    float sn, c; sincosf(fr, &sn, &c);
    float x1 = q[2 * i], x2 = q[2 * i + 1];
    q[2 * i]     = x1 * c - x2 * sn;
    q[2 * i + 1] = x1 * sn + x2 * c;
}

// ---------------- pack Q/K/V into [b,h,s,d]; fold softmax scale into Q ----
__global__ void pack_k(const float* __restrict__ qn, const float* __restrict__ qp,
                       const float* __restrict__ kvu, const float* __restrict__ kr,
                       float* __restrict__ Q, float* __restrict__ K, float* __restrict__ V)
{
    int bsh = blockIdx.x;
    int h = bsh % H_;
    int bs = bsh / H_;
    int b = bs / S_, s = bs % S_;
    long long out = ((long long)(b * H_ + h) * S_ + s);
    const float scale = 0.07216878364870323f;   // 1/sqrt(192)
    for (int d = threadIdx.x; d < QKD; d += 256) {
        float qv = (d < NOPE_)
            ? qn[(long long)bs * (H_ * NOPE_) + h * NOPE_ + d]
            : qp[(long long)bs * (H_ * ROPE_) + h * ROPE_ + (d - NOPE_)];
        Q[out * QKD + d] = qv * scale;
        float kv = (d < NOPE_)
            ? kvu[(long long)bs * (H_ * (NOPE_ + VDIM_)) + h * (NOPE_ + VDIM_) + d]
            : kr[(long long)bs * ROPE_ + (d - NOPE_)];
        K[out * QKD + d] = kv;
    }
    for (int v = threadIdx.x; v < VDIM_; v += 256) {
        V[out * VDIM_ + v] =
            kvu[(long long)bs * (H_ * (NOPE_ + VDIM_)) + h * (NOPE_ + VDIM_) + NOPE_ + v];
    }
}

// ---------------- causal softmax (in-place), zero-fill to 128-boundary ----
__global__ void softmax_causal(float* __restrict__ sc)
{
    int i = blockIdx.x;
    long long bh = blockIdx.y;
    float* row = sc + (bh * S_ + i) * (long long)S_;
    int len = i + 1;
    int tid = threadIdx.x;
    __shared__ float red[256];

    float mx = -1e30f;
    for (int j = tid; j < len; j += 256) mx = fmaxf(mx, row[j]);
    red[tid] = mx; __syncthreads();
    for (int s = 128; s > 0; s >>= 1) { if (tid < s) red[tid] = fmaxf(red[tid], red[tid + s]); __syncthreads(); }
    mx = red[0]; __syncthreads();

    float sum = 0.f;
    for (int j = tid; j < len; j += 256) { float e = expf(row[j] - mx); row[j] = e; sum += e; }
    red[tid] = sum; __syncthreads();
    for (int s = 128; s > 0; s >>= 1) { if (tid < s) red[tid] += red[tid + s]; __syncthreads(); }
    float inv = 1.f / red[0];

    for (int j = tid; j < len; j += 256) row[j] *= inv;
    int rounded = (len + 127) & ~127;
    for (int j = len + tid; j < rounded; j += 256) row[j] = 0.f;
}

// ---------------- launch ----------------
extern "C" void kernel_launch(void* const* d_in, const int* in_sizes, int n_in,
                              void* d_out, int out_size)
{
    const float* x        = (const float*)d_in[0];
    const float* wq_down  = (const float*)d_in[1];
    const float* q_norm   = (const float*)d_in[2];
    const float* wq_up    = (const float*)d_in[3];
    const float* wq_rope  = (const float*)d_in[4];
    const float* wkv_down = (const float*)d_in[5];
    const float* kv_norm  = (const float*)d_in[6];
    const float* wkv_up   = (const float*)d_in[7];
    const float* wk_rope  = (const float*)d_in[8];
    const float* wo       = (const float*)d_in[9];
    float* out = (float*)d_out;

    float *qc, *qn, *qp, *kvc, *kvu, *kr, *Q, *K, *V, *sc, *attn;
    cudaGetSymbolAddress((void**)&qc,   g_qc);
    cudaGetSymbolAddress((void**)&qn,   g_qnope);
    cudaGetSymbolAddress((void**)&qp,   g_qpe);
    cudaGetSymbolAddress((void**)&kvc,  g_kvc);
    cudaGetSymbolAddress((void**)&kvu,  g_kvup);
    cudaGetSymbolAddress((void**)&kr,   g_krope);
    cudaGetSymbolAddress((void**)&Q,    g_Q);
    cudaGetSymbolAddress((void**)&K,    g_K);
    cudaGetSymbolAddress((void**)&V,    g_V);
    cudaGetSymbolAddress((void**)&sc,   g_sc);
    cudaGetSymbolAddress((void**)&attn, g_attn);

    dim3 blk(256);

    // q_c = rmsnorm(x @ wq_down^T)
    gemm_tf32<true,0,false><<<dim3(QR_/128, MTOK/128, 1), blk>>>(x, wq_down, qc, MTOK, QR_, DIM_, 0, 0, 0);
    rmsnorm_k<<<MTOK, 256>>>(qc, q_norm, QR_);
    // q_nope = q_c @ wq_up^T ; q_pe = q_c @ wq_rope^T
    gemm_tf32<true,0,false><<<dim3((H_*NOPE_)/128, MTOK/128, 1), blk>>>(qc, wq_up,   qn, MTOK, H_*NOPE_, QR_, 0, 0, 0);
    gemm_tf32<true,0,false><<<dim3((H_*ROPE_)/128, MTOK/128, 1), blk>>>(qc, wq_rope, qp, MTOK, H_*ROPE_, QR_, 0, 0, 0);
    // kv_c = rmsnorm(x @ wkv_down^T); kv_up = kv_c @ wkv_up^T
    gemm_tf32<true,0,false><<<dim3(KVR_/128, MTOK/128, 1), blk>>>(x, wkv_down, kvc, MTOK, KVR_, DIM_, 0, 0, 0);
    rmsnorm_k<<<MTOK, 256>>>(kvc, kv_norm, KVR_);
    gemm_tf32<true,0,false><<<dim3((H_*(NOPE_+VDIM_))/128, MTOK/128, 1), blk>>>(kvc, wkv_up, kvu, MTOK, H_*(NOPE_+VDIM_), KVR_, 0, 0, 0);
    // shared k_rope = x @ wk_rope^T  (N=64 -> fp32 fallback)
    gemm64<<<dim3(ROPE_/64, MTOK/64, 1), blk>>>(x, wk_rope, kr, MTOK, ROPE_, DIM_);
    // RoPE
    rope_q_k <<<MTOK, 256>>>(qp);
    rope_kr_k<<<MTOK, 32>>>(kr);
    // pack Q/K/V [b,h,s,d]
    pack_k<<<MTOK * H_, 256>>>(qn, qp, kvu, kr, Q, K, V);
    // scores = Q @ K^T (batched over b*h, causal block skip)
    gemm_tf32<true,1,false><<<dim3(S_/128, S_/128, BH_), blk>>>(
        Q, K, sc, S_, S_, QKD,
        (long long)S_*QKD, (long long)S_*QKD, (long long)S_*S_);
    // causal softmax
    softmax_causal<<<dim3(S_, BH_), 256>>>(sc);
    // attn = P @ V (batched, causal K limit, write into [b,s,h*v])
    gemm_tf32<false,2,true><<<dim3(VDIM_/128, S_/128, BH_), blk>>>(
        sc, V, attn, S_, VDIM_, S_,
        (long long)S_*S_, (long long)S_*VDIM_, 0);
    // out = attn @ wo^T
    gemm_tf32<true,0,false><<<dim3(DIM_/128, MTOK/128, 1), blk>>>(attn, wo, out, MTOK, DIM_, DIM_, 0, 0, 0);
}

// round 3
// speedup vs baseline: 2.0555x; 1.2515x over previous
#include <cuda_runtime.h>
#include <math.h>
#include <mma.h>
using namespace nvcuda;

// ---------------- problem constants ----------------
#define B_    2
#define S_    2048
#define DIM_  2048
#define H_    16
#define NOPE_ 128
#define ROPE_ 64
#define VDIM_ 128
#define QR_   1024
#define KVR_  512
#define MTOK  (B_*S_)          // 4096
#define QKD   (NOPE_+ROPE_)    // 192
#define BH_   (B_*H_)          // 32

// ---------------- scratch ----------------
__device__ float g_qc   [(long long)MTOK*QR_];
__device__ float g_qnope[(long long)MTOK*H_*NOPE_];
__device__ float g_qpe  [(long long)MTOK*H_*ROPE_];
__device__ float g_kvc  [(long long)MTOK*KVR_];
__device__ float g_kvup [(long long)MTOK*H_*(NOPE_+VDIM_)];
__device__ float g_krope[(long long)MTOK*ROPE_];
__device__ float g_attn [(long long)MTOK*H_*VDIM_];

// ---------------- helpers ----------------
__device__ __forceinline__ unsigned f2tf(float f) {
    unsigned r; asm("cvt.rna.tf32.f32 %0, %1;" : "=r"(r) : "f"(f)); return r;
}
__device__ __forceinline__ float rtf(float x) { return __uint_as_float(f2tf(x)); }

__device__ __forceinline__ void mma_tf32(float c[4], const unsigned a[4], const unsigned b[2]) {
    asm volatile(
        "mma.sync.aligned.m16n8k8.row.col.f32.tf32.tf32.f32 "
        "{%0,%1,%2,%3},{%4,%5,%6,%7},{%8,%9},{%0,%1,%2,%3};"
        : "+f"(c[0]), "+f"(c[1]), "+f"(c[2]), "+f"(c[3])
        : "r"(a[0]), "r"(a[1]), "r"(a[2]), "r"(a[3]), "r"(b[0]), "r"(b[1]));
}

__device__ __forceinline__ void cpasync16(void* s, const void* g) {
    unsigned saddr = (unsigned)__cvta_generic_to_shared(s);
    asm volatile("cp.async.ca.shared.global [%0], [%1], 16;" :: "r"(saddr), "l"(g));
}

// =====================================================================
// NT TF32 GEMM with cp.async 2-stage double buffering.
// C[M,N] = A[M,K] * B^T, B stored [N,K]. Tiles 128x128x32, 8 warps.
// =====================================================================
__device__ __forceinline__ void gemm_issue(const float* A, const float* B,
                                           float* SA, float* SB,
                                           int bm, int bn, int K, int kt, int st, int tid)
{
    const int k0 = kt << 5;
    #pragma unroll
    for (int l = 0; l < 4; l++) {
        int idx = tid + (l << 8);
        int r = idx >> 3, c4 = (idx & 7) << 2;
        cpasync16(&SA[st * 4608 + r * 36 + c4], &A[(long long)(bm * 128 + r) * K + k0 + c4]);
    }
    #pragma unroll
    for (int l = 0; l < 4; l++) {
        int idx = tid + (l << 8);
        int r = idx >> 3, c4 = (idx & 7) << 2;
        cpasync16(&SB[st * 4608 + r * 36 + c4], &B[(long long)(bn * 128 + r) * K + k0 + c4]);
    }
    asm volatile("cp.async.commit_group;");
}

__global__ __launch_bounds__(256, 2)
void gemm_nt(const float* __restrict__ A, const float* __restrict__ Bm,
             float* __restrict__ C, int M, int N, int K)
{
    extern __shared__ float smg[];
    float* SA = smg;                // [2][128*36]
    float* SB = smg + 2 * 4608;

    const int bm = blockIdx.y, bn = blockIdx.x;
    const int tid = threadIdx.x;
    const int w = tid >> 5;
    const int wm = w >> 2, wn = w & 3;

    wmma::fragment<wmma::accumulator, 16, 16, 8, float> cf[4][2];
    #pragma unroll
    for (int i = 0; i < 4; i++)
        #pragma unroll
        for (int j = 0; j < 2; j++)
            wmma::fill_fragment(cf[i][j], 0.0f);

    const int nk = K >> 5;
    gemm_issue(A, Bm, SA, SB, bm, bn, K, 0, 0, tid);

    for (int kt = 0; kt < nk; kt++) {
        const int st = kt & 1;
        if (kt + 1 < nk) {
            gemm_issue(A, Bm, SA, SB, bm, bn, K, kt + 1, st ^ 1, tid);
            asm volatile("cp.async.wait_group 1;");
        } else {
            asm volatile("cp.async.wait_group 0;");
        }
        __syncthreads();

        float* As = SA + st * 4608;
        float* Bs = SB + st * 4608;
        #pragma unroll
        for (int kk = 0; kk < 4; kk++) {
            wmma::fragment<wmma::matrix_a, 16, 16, 8, wmma::precision::tf32, wmma::row_major> af[4];
            #pragma unroll
            for (int i = 0; i < 4; i++) {
                wmma::load_matrix_sync(af[i], &As[(wm * 64 + i * 16) * 36 + kk * 8], 36);
                #pragma unroll
                for (int t = 0; t < af[i].num_elements; t++)
                    af[i].x[t] = wmma::__float_to_tf32(af[i].x[t]);
            }
            wmma::fragment<wmma::matrix_b, 16, 16, 8, wmma::precision::tf32, wmma::col_major> bf[2];
            #pragma unroll
            for (int j = 0; j < 2; j++) {
                wmma::load_matrix_sync(bf[j], &Bs[(wn * 32 + j * 16) * 36 + kk * 8], 36);
                #pragma unroll
                for (int t = 0; t < bf[j].num_elements; t++)
                    bf[j].x[t] = wmma::__float_to_tf32(bf[j].x[t]);
            }
            #pragma unroll
            for (int i = 0; i < 4; i++)
                #pragma unroll
                for (int j = 0; j < 2; j++)
                    wmma::mma_sync(cf[i][j], af[i], bf[j], cf[i][j]);
        }
        __syncthreads();
    }

    #pragma unroll
    for (int i = 0; i < 4; i++)
        #pragma unroll
        for (int j = 0; j < 2; j++)
            wmma::store_matrix_sync(
                &C[(long long)(bm * 128 + wm * 64 + i * 16) * N + bn * 128 + wn * 32 + j * 16],
                cf[i][j], (unsigned)N, wmma::mem_row_major);
}

// =====================================================================
// Fused flash attention (tf32 mma, online softmax).
// Q tile 128 rows, KV tiles of 64. One block per (q-tile, b*h).
// Inputs read directly from projection outputs; O written to g_attn [bs][h*128+c].
// =====================================================================
__global__ __launch_bounds__(256, 1)
void flash_attn(const float* __restrict__ qn, const float* __restrict__ qp,
                const float* __restrict__ kvu, const float* __restrict__ kr,
                float* __restrict__ outp)
{
    extern __shared__ float sm[];
    float* QS   = sm;          // [128][196]
    float* KS   = sm + 25088;  // [64][196]
    float* VS   = sm + 37632;  // [64][132]
    float* PS   = sm + 46080;  // [128][68]
    float* PMAX = sm + 54784;  // [2][128]
    float* PSUM = sm + 55040;  // [2][128]
    float* MR   = sm + 55296;  // [128]
    float* LR   = sm + 55424;  // [128]
    float* CR   = sm + 55552;  // [128]

    const int qt = (int)gridDim.x - 1 - (int)blockIdx.x;   // big tiles first
    const int bh = blockIdx.y;
    const int b = bh >> 4, h = bh & 15;
    const int ib = qt * 128;
    const long long bs0 = (long long)b * S_;

    const int tid = threadIdx.x;
    const int w = tid >> 5, lane = tid & 31;
    const int wm = w & 3, wn = w >> 2;
    const int g = lane >> 2, t = lane & 3;
    const float scale = 0.07216878364870323f;  // 1/sqrt(192)

    // ---- load Q tile (scaled + tf32-rounded) ----
    for (int i = tid; i < 128 * 48; i += 256) {
        int r = i / 48, c4 = (i % 48) * 4;
        long long row = bs0 + ib + r;
        float4 v;
        if (c4 < 128) v = *(const float4*)&qn[row * 2048 + h * 128 + c4];
        else          v = *(const float4*)&qp[row * 1024 + h * 64 + (c4 - 128)];
        float* d = &QS[r * 196 + c4];
        d[0] = rtf(v.x * scale); d[1] = rtf(v.y * scale);
        d[2] = rtf(v.z * scale); d[3] = rtf(v.w * scale);
    }
    if (tid < 128) { MR[tid] = -1e30f; LR[tid] = 0.f; }

    float oacc[2][8][4] = {};

    const int ntiles = (ib + 128) / 64;
    for (int kt = 0; kt < ntiles; kt++) {
        const int jb = kt * 64;
        __syncthreads();   // Q ready (iter 0) / previous PV done

        // ---- load K tile (tf32-rounded) ----
        for (int i = tid; i < 64 * 48; i += 256) {
            int r = i / 48, c4 = (i % 48) * 4;
            long long row = bs0 + jb + r;
            float4 v;
            if (c4 < 128) v = *(const float4*)&kvu[row * 4096 + h * 256 + c4];
            else          v = *(const float4*)&kr[row * 64 + (c4 - 128)];
            float* d = &KS[r * 196 + c4];
            d[0] = rtf(v.x); d[1] = rtf(v.y); d[2] = rtf(v.z); d[3] = rtf(v.w);
        }
        // ---- load V tile (tf32-rounded) ----
        for (int i = tid; i < 64 * 32; i += 256) {
            int r = i / 32, c4 = (i % 32) * 4;
            long long row = bs0 + jb + r;
            float4 v = *(const float4*)&kvu[row * 4096 + h * 256 + 128 + c4];
            float* d = &VS[r * 132 + c4];
            d[0] = rtf(v.x); d[1] = rtf(v.y); d[2] = rtf(v.z); d[3] = rtf(v.w);
        }
        __syncthreads();

        // ---- S = Q K^T  (warp tile 32x32: mf 2 x nf 4) ----
        float sacc[2][4][4] = {};
        #pragma unroll
        for (int k = 0; k < 24; k++) {
            unsigned a[2][4];
            #pragma unroll
            for (int mf = 0; mf < 2; mf++) {
                int r0 = wm * 32 + mf * 16 + g;
                a[mf][0] = __float_as_uint(QS[r0 * 196 + k * 8 + t]);
                a[mf][1] = __float_as_uint(QS[(r0 + 8) * 196 + k * 8 + t]);
                a[mf][2] = __float_as_uint(QS[r0 * 196 + k * 8 + t + 4]);
                a[mf][3] = __float_as_uint(QS[(r0 + 8) * 196 + k * 8 + t + 4]);
            }
            #pragma unroll
            for (int nf = 0; nf < 4; nf++) {
                unsigned bb[2];
                int n0 = wn * 32 + nf * 8 + g;
                bb[0] = __float_as_uint(KS[n0 * 196 + k * 8 + t]);
                bb[1] = __float_as_uint(KS[n0 * 196 + k * 8 + t + 4]);
                mma_tf32(sacc[0][nf], a[0], bb);
                mma_tf32(sacc[1][nf], a[1], bb);
            }
        }

        // ---- causal mask ----
        if (jb + 63 > ib) {
            #pragma unroll
            for (int mf = 0; mf < 2; mf++)
                #pragma unroll
                for (int nf = 0; nf < 4; nf++)
                    #pragma unroll
                    for (int e = 0; e < 4; e++) {
                        int row = ib + wm * 32 + mf * 16 + g + ((e >> 1) << 3);
                        int col = jb + wn * 32 + nf * 8 + 2 * t + (e & 1);
                        if (col > row) sacc[mf][nf][e] = -1e30f;
                    }
        }

        // ---- per-row max (slots: mf x half) ----
        float rmax[2][2];
        #pragma unroll
        for (int mf = 0; mf < 2; mf++)
            #pragma unroll
            for (int hf = 0; hf < 2; hf++) {
                float v = -1e30f;
                #pragma unroll
                for (int nf = 0; nf < 4; nf++)
                    v = fmaxf(v, fmaxf(sacc[mf][nf][2 * hf], sacc[mf][nf][2 * hf + 1]));
                v = fmaxf(v, __shfl_xor_sync(0xFFFFFFFF, v, 1));
                v = fmaxf(v, __shfl_xor_sync(0xFFFFFFFF, v, 2));
                rmax[mf][hf] = v;
            }
        if (t == 0) {
            #pragma unroll
            for (int mf = 0; mf < 2; mf++)
                #pragma unroll
                for (int hf = 0; hf < 2; hf++)
                    PMAX[wn * 128 + wm * 32 + mf * 16 + hf * 8 + g] = rmax[mf][hf];
        }
        __syncthreads();

        if (tid < 128) {
            float mo = MR[tid];
            float mn = fmaxf(mo, fmaxf(PMAX[tid], PMAX[128 + tid]));
            MR[tid] = mn;
            CR[tid] = __expf(mo - mn);
        }
        __syncthreads();

        // ---- P = exp(S - m), partial sums, store to PS (tf32) ----
        float rsum[2][2] = {};
        #pragma unroll
        for (int mf = 0; mf < 2; mf++) {
            int r0 = wm * 32 + mf * 16 + g;
            float m0 = MR[r0], m1 = MR[r0 + 8];
            #pragma unroll
            for (int nf = 0; nf < 4; nf++) {
                float p0 = __expf(sacc[mf][nf][0] - m0);
                float p1 = __expf(sacc[mf][nf][1] - m0);
                float p2 = __expf(sacc[mf][nf][2] - m1);
                float p3 = __expf(sacc[mf][nf][3] - m1);
                rsum[mf][0] += p0 + p1;
                rsum[mf][1] += p2 + p3;
                int c0 = wn * 32 + nf * 8 + 2 * t;
                PS[r0 * 68 + c0]           = rtf(p0);
                PS[r0 * 68 + c0 + 1]       = rtf(p1);
                PS[(r0 + 8) * 68 + c0]     = rtf(p2);
                PS[(r0 + 8) * 68 + c0 + 1] = rtf(p3);
            }
        }
        #pragma unroll
        for (int mf = 0; mf < 2; mf++)
            #pragma unroll
            for (int hf = 0; hf < 2; hf++) {
                float v = rsum[mf][hf];
                v += __shfl_xor_sync(0xFFFFFFFF, v, 1);
                v += __shfl_xor_sync(0xFFFFFFFF, v, 2);
                rsum[mf][hf] = v;
            }
        if (t == 0) {
            #pragma unroll
            for (int mf = 0; mf < 2; mf++)
                #pragma unroll
                for (int hf = 0; hf < 2; hf++)
                    PSUM[wn * 128 + wm * 32 + mf * 16 + hf * 8 + g] = rsum[mf][hf];
        }

        // ---- rescale O by c ----
        #pragma unroll
        for (int mf = 0; mf < 2; mf++) {
            float c0 = CR[wm * 32 + mf * 16 + g];
            float c1 = CR[wm * 32 + mf * 16 + g + 8];
            #pragma unroll
            for (int nf = 0; nf < 8; nf++) {
                oacc[mf][nf][0] *= c0; oacc[mf][nf][1] *= c0;
                oacc[mf][nf][2] *= c1; oacc[mf][nf][3] *= c1;
            }
        }
        __syncthreads();

        if (tid < 128)
            LR[tid] = LR[tid] * CR[tid] + PSUM[tid] + PSUM[128 + tid];

        // ---- O += P V  (warp tile 32x64: mf 2 x nf 8) ----
        #pragma unroll
        for (int k = 0; k < 8; k++) {
            unsigned a[2][4];
            #pragma unroll
            for (int mf = 0; mf < 2; mf++) {
                int r0 = wm * 32 + mf * 16 + g;
                a[mf][0] = __float_as_uint(PS[r0 * 68 + k * 8 + t]);
                a[mf][1] = __float_as_uint(PS[(r0 + 8) * 68 + k * 8 + t]);
                a[mf][2] = __float_as_uint(PS[r0 * 68 + k * 8 + t + 4]);
                a[mf][3] = __float_as_uint(PS[(r0 + 8) * 68 + k * 8 + t + 4]);
            }
            #pragma unroll
            for (int nf = 0; nf < 8; nf++) {
                unsigned bb[2];
                int n0 = wn * 64 + nf * 8 + g;
                bb[0] = __float_as_uint(VS[(k * 8 + t) * 132 + n0]);
                bb[1] = __float_as_uint(VS[(k * 8 + t + 4) * 132 + n0]);
                mma_tf32(oacc[0][nf], a[0], bb);
                mma_tf32(oacc[1][nf], a[1], bb);
            }
        }
    }
    __syncthreads();

    // ---- epilogue: O / l -> g_attn [bs][h*128 + c] ----
    #pragma unroll
    for (int mf = 0; mf < 2; mf++) {
        int r0 = wm * 32 + mf * 16 + g;
        float inv0 = 1.f / LR[r0];
        float inv1 = 1.f / LR[r0 + 8];
        long long o0 = (bs0 + ib + r0) * 2048 + h * 128 + wn * 64;
        long long o1 = (bs0 + ib + r0 + 8) * 2048 + h * 128 + wn * 64;
        #pragma unroll
        for (int nf = 0; nf < 8; nf++) {
            int c = nf * 8 + 2 * t;
            float2 v0 = make_float2(oacc[mf][nf][0] * inv0, oacc[mf][nf][1] * inv0);
            float2 v1 = make_float2(oacc[mf][nf][2] * inv1, oacc[mf][nf][3] * inv1);
            *(float2*)&outp[o0 + c] = v0;
            *(float2*)&outp[o1 + c] = v1;
        }
    }
}

// ---------------- fp32 SGEMM for tiny k_rope (N=64) ----------------
__global__ void gemm64(const float* __restrict__ A, const float* __restrict__ Bm,
                       float* __restrict__ C, int M, int N, int K)
{
    const int bm = blockIdx.y, bn = blockIdx.x;
    __shared__ float As[64 * 33];
    __shared__ float Bs[64 * 33];
    const int tid = threadIdx.x;
    const int tx = tid & 15, ty = tid >> 4;
    float acc[4][4] = {};
    for (int k0 = 0; k0 < K; k0 += 32) {
        #pragma unroll
        for (int l = 0; l < 8; l++) {
            int idx = tid + l * 256;
            int r = idx >> 5, c = idx & 31;
            As[r * 33 + c] = A[(long long)(bm * 64 + r) * K + k0 + c];
            Bs[r * 33 + c] = Bm[(long long)(bn * 64 + r) * K + k0 + c];
        }
        __syncthreads();
        #pragma unroll
        for (int kk = 0; kk < 32; kk++) {
            float a[4], b[4];
            #pragma unroll
            for (int i = 0; i < 4; i++) a[i] = As[(ty * 4 + i) * 33 + kk];
            #pragma unroll
            for (int j = 0; j < 4; j++) b[j] = Bs[(tx * 4 + j) * 33 + kk];
            #pragma unroll
            for (int i = 0; i < 4; i++)
                #pragma unroll
                for (int j = 0; j < 4; j++)
                    acc[i][j] += a[i] * b[j];
        }
        __syncthreads();
    }
    #pragma unroll
    for (int i = 0; i < 4; i++)
        #pragma unroll
        for (int j = 0; j < 4; j++)
            C[(long long)(bm * 64 + ty * 4 + i) * N + bn * 64 + tx * 4 + j] = acc[i][j];
}

// ---------------- RMSNorm ----------------
__global__ void rmsnorm_k(float* __restrict__ x, const float* __restrict__ w, int N)
{
    float* p = x + (long long)blockIdx.x * N;
    int tid = threadIdx.x;
    float ss = 0.f;
    for (int i = tid; i < N; i += 256) { float v = p[i]; ss += v * v; }
    __shared__ float red[256];
    red[tid] = ss; __syncthreads();
    for (int s = 128; s > 0; s >>= 1) { if (tid < s) red[tid] += red[tid + s]; __syncthreads(); }
    float scale = rsqrtf(red[0] / N + 1e-6f);
    for (int i = tid; i < N; i += 256) p[i] = p[i] * scale * w[i];
}

// ---------------- RoPE on q_pe [MTOK, H*ROPE] ----------------
__global__ void rope_q_k(float* __restrict__ qpe)
{
    int row = blockIdx.x;
    int s = row % S_;
    float* base = qpe + (long long)row * (H_ * ROPE_);
    for (int idx = threadIdx.x; idx < H_ * (ROPE_ / 2); idx += 256) {
        int h = idx >> 5, i = idx & 31;
        float fr = (float)s * powf(10000.f, -(2.f * i) / (float)ROPE_);
        float sn, c; sincosf(fr, &sn, &c);
        float* q = base + h * ROPE_;
        float x1 = q[2 * i], x2 = q[2 * i + 1];
        q[2 * i]     = x1 * c - x2 * sn;
        q[2 * i + 1] = x1 * sn + x2 * c;
    }
}

// ---------------- RoPE on k_rope [MTOK, ROPE] ----------------
__global__ void rope_kr_k(float* __restrict__ kr)
{
    int row = blockIdx.x;
    int s = row % S_;
    float* q = kr + (long long)row * ROPE_;
    int i = threadIdx.x;
    float fr = (float)s * powf(10000.f, -(2.f * i) / (float)ROPE_);
    float sn, c; sincosf(fr, &sn, &c);
    float x1 = q[2 * i], x2 = q[2 * i + 1];
    q[2 * i]     = x1 * c - x2 * sn;
    q[2 * i + 1] = x1 * sn + x2 * c;
}

// ---------------- launch ----------------
extern "C" void kernel_launch(void* const* d_in, const int* in_sizes, int n_in,
                              void* d_out, int out_size)
{
    const float* x        = (const float*)d_in[0];
    const float* wq_down  = (const float*)d_in[1];
    const float* q_norm   = (const float*)d_in[2];
    const float* wq_up    = (const float*)d_in[3];
    const float* wq_rope  = (const float*)d_in[4];
    const float* wkv_down = (const float*)d_in[5];
    const float* kv_norm  = (const float*)d_in[6];
    const float* wkv_up   = (const float*)d_in[7];
    const float* wk_rope  = (const float*)d_in[8];
    const float* wo       = (const float*)d_in[9];
    float* out = (float*)d_out;

    float *qc, *qn, *qp, *kvc, *kvu, *kr, *attn;
    cudaGetSymbolAddress((void**)&qc,   g_qc);
    cudaGetSymbolAddress((void**)&qn,   g_qnope);
    cudaGetSymbolAddress((void**)&qp,   g_qpe);
    cudaGetSymbolAddress((void**)&kvc,  g_kvc);
    cudaGetSymbolAddress((void**)&kvu,  g_kvup);
    cudaGetSymbolAddress((void**)&kr,   g_krope);
    cudaGetSymbolAddress((void**)&attn, g_attn);

    static int attr_set = 0;
    if (!attr_set) {
        cudaFuncSetAttribute(gemm_nt, cudaFuncAttributeMaxDynamicSharedMemorySize, 73728);
        cudaFuncSetAttribute(flash_attn, cudaFuncAttributeMaxDynamicSharedMemorySize, 222720);
        attr_set = 1;
    }

    dim3 blk(256);
    const int GS = 73728;      // gemm smem
    const int FS = 222720;     // flash smem

    // q_c = rmsnorm(x @ wq_down^T)
    gemm_nt<<<dim3(QR_/128, MTOK/128), blk, GS>>>(x, wq_down, qc, MTOK, QR_, DIM_);
    rmsnorm_k<<<MTOK, 256>>>(qc, q_norm, QR_);
    // q_nope / q_pe
    gemm_nt<<<dim3((H_*NOPE_)/128, MTOK/128), blk, GS>>>(qc, wq_up,   qn, MTOK, H_*NOPE_, QR_);
    gemm_nt<<<dim3((H_*ROPE_)/128, MTOK/128), blk, GS>>>(qc, wq_rope, qp, MTOK, H_*ROPE_, QR_);
    // kv path
    gemm_nt<<<dim3(KVR_/128, MTOK/128), blk, GS>>>(x, wkv_down, kvc, MTOK, KVR_, DIM_);
    rmsnorm_k<<<MTOK, 256>>>(kvc, kv_norm, KVR_);
    gemm_nt<<<dim3((H_*(NOPE_+VDIM_))/128, MTOK/128), blk, GS>>>(kvc, wkv_up, kvu, MTOK, H_*(NOPE_+VDIM_), KVR_);
    // shared k_rope
    gemm64<<<dim3(ROPE_/64, MTOK/64), blk>>>(x, wk_rope, kr, MTOK, ROPE_, DIM_);
    // RoPE
    rope_q_k <<<MTOK, 256>>>(qp);
    rope_kr_k<<<MTOK, 32>>>(kr);
    // fused attention -> attn [bs][h*128+c]
    flash_attn<<<dim3(S_/128, BH_), blk, FS>>>(qn, qp, kvu, kr, attn);
    // out = attn @ wo^T
    gemm_nt<<<dim3(DIM_/128, MTOK/128), blk, GS>>>(attn, wo, out, MTOK, DIM_, DIM_);
}